// round 1
// baseline (speedup 1.0000x reference)
#include <cuda_runtime.h>

// Shapes (fixed by the problem)
#define BB   4
#define TT   512
#define FF   93
#define DSS  64
#define DD   1024
#define HH   8
#define MM   (BB*TT)      // 2048 rows

// Scratch (static device allocations; no cudaMalloc allowed)
__device__ float g_y0pre[MM*DSS];        // spectral fct output pre-Wos  [2048,64]
__device__ float g_WosWt[DSS*DD];        // Wos @ Wt                     [64,1024]
__device__ float g_xt[MM*DD];            // temporal stream input        [2048,1024]
__device__ float g_qkv[3*MM*DD];         // Q,K,V                        [3,2048,1024]
__device__ float g_attnout[MM*DD];       // temporal attention output    [2048,1024]

// ---------------------------------------------------------------------------
// WosWt = Wos[64,64] @ Wt[64,1024]
// ---------------------------------------------------------------------------
__global__ void woswt_kernel(const float* __restrict__ Wos, const float* __restrict__ Wt) {
    int idx = blockIdx.x * 256 + threadIdx.x;   // 65536 outputs
    int r = idx >> 10, c = idx & 1023;
    float s = 0.f;
    #pragma unroll 8
    for (int k = 0; k < 64; k++) s += Wos[r*64 + k] * Wt[k*1024 + c];
    g_WosWt[idx] = s;
}

// ---------------------------------------------------------------------------
// Spectral attention, fct query only.
// For each (b,t): q0 = xs[0,:]@Wqs; score[h][j] = xs[j,:]·qW[h,:] where
// qW folds Wks into q0; softmax over j (row 0 mask = all True);
// a[h][k] = sum_j p*xs[j][k]; out = a@Wvs (per head column block).
// ---------------------------------------------------------------------------
__global__ void spectral_kernel(const float* __restrict__ xs,
                                const float* __restrict__ Wqs,
                                const float* __restrict__ Wks,
                                const float* __restrict__ Wvs) {
    __shared__ float xs_s[FF*65];
    __shared__ float q0_s[64];
    __shared__ float qW_s[8*64];
    __shared__ float p_s[8*96];
    __shared__ float a_s[8*64];

    const int bt  = blockIdx.x;
    const int tid = threadIdx.x;   // 256
    const float* xp = xs + (size_t)bt * FF * DSS;

    for (int idx = tid; idx < FF*DSS; idx += 256)
        xs_s[(idx >> 6) * 65 + (idx & 63)] = xp[idx];
    __syncthreads();

    if (tid < 64) {
        float s = 0.f;
        #pragma unroll 8
        for (int k = 0; k < 64; k++) s += xs_s[k] * __ldg(&Wqs[k*64 + tid]);
        q0_s[tid] = s;
    }
    __syncthreads();

    // qW[h][k] = sum_d q0[h*8+d] * Wks[k][h*8+d]
    for (int idx = tid; idx < 512; idx += 256) {
        int h = idx >> 6, k = idx & 63;
        float s = 0.f;
        #pragma unroll
        for (int d = 0; d < 8; d++) s += q0_s[h*8 + d] * __ldg(&Wks[k*64 + h*8 + d]);
        qW_s[idx] = s;
    }
    __syncthreads();

    // scores
    const float scale = 0.35355339059327376f;   // 1/sqrt(8)
    for (int idx = tid; idx < 8*FF; idx += 256) {
        int h = idx / FF, j = idx - h * FF;
        float s = 0.f;
        #pragma unroll 8
        for (int k = 0; k < 64; k++) s += xs_s[j*65 + k] * qW_s[h*64 + k];
        p_s[h*96 + j] = s * scale;
    }
    __syncthreads();

    // softmax over j, one warp per head
    {
        int w = tid >> 5, lane = tid & 31;
        float m = -3.0e38f;
        for (int j = lane; j < FF; j += 32) m = fmaxf(m, p_s[w*96 + j]);
        #pragma unroll
        for (int o = 16; o > 0; o >>= 1) m = fmaxf(m, __shfl_xor_sync(0xffffffffu, m, o));
        float sum = 0.f;
        for (int j = lane; j < FF; j += 32) {
            float e = __expf(p_s[w*96 + j] - m);
            p_s[w*96 + j] = e; sum += e;
        }
        #pragma unroll
        for (int o = 16; o > 0; o >>= 1) sum += __shfl_xor_sync(0xffffffffu, sum, o);
        float inv = 1.f / sum;
        for (int j = lane; j < FF; j += 32) p_s[w*96 + j] *= inv;
    }
    __syncthreads();

    // a[h][k] = sum_j p[h][j] * xs[j][k]
    for (int idx = tid; idx < 512; idx += 256) {
        int h = idx >> 6, k = idx & 63;
        float s = 0.f;
        for (int j = 0; j < FF; j++) s += p_s[h*96 + j] * xs_s[j*65 + k];
        a_s[idx] = s;
    }
    __syncthreads();

    // out0[c] (c = h*8+d) = sum_k a[h][k]*Wvs[k][c]
    if (tid < 64) {
        int h = tid >> 3;
        float s = 0.f;
        #pragma unroll 8
        for (int k = 0; k < 64; k++) s += a_s[h*64 + k] * __ldg(&Wvs[k*64 + tid]);
        g_y0pre[bt*64 + tid] = s;
    }
}

// ---------------------------------------------------------------------------
// xt = x + y0pre @ WosWt     (rank-64 update, one block per row)
// ---------------------------------------------------------------------------
__global__ void xt_kernel(const float* __restrict__ x) {
    int row = blockIdx.x;
    int tid = threadIdx.x;     // 256
    __shared__ float y0[64];
    if (tid < 64) y0[tid] = g_y0pre[row*64 + tid];
    __syncthreads();

    int c = tid * 4;
    float4 acc = *(const float4*)(x + (size_t)row*DD + c);
    #pragma unroll 8
    for (int k = 0; k < 64; k++) {
        float y = y0[k];
        float4 w = *(const float4*)(g_WosWt + k*DD + c);
        acc.x += y * w.x; acc.y += y * w.y; acc.z += y * w.z; acc.w += y * w.w;
    }
    *(float4*)(g_xt + (size_t)row*DD + c) = acc;
}

// ---------------------------------------------------------------------------
// SGEMM tile: C[M,1024] = A[M,1024] @ W[1024,1024], row-major.
// 128x128 block tile, BK=16, 256 threads, 8x8 per thread.
// ---------------------------------------------------------------------------
__device__ __forceinline__ void gemm_tile(const float* __restrict__ A,
                                          const float* __restrict__ Bw,
                                          float* __restrict__ C,
                                          int bm, int bn) {
    __shared__ float As[16][132];
    __shared__ float Bs[16][128];
    const int tid = threadIdx.x;
    const int ty  = tid >> 4;   // 0..15  (row group)
    const int tx  = tid & 15;   // 0..15  (col group)

    float acc[8][8];
    #pragma unroll
    for (int i = 0; i < 8; i++)
        #pragma unroll
        for (int j = 0; j < 8; j++) acc[i][j] = 0.f;

    for (int k0 = 0; k0 < 1024; k0 += 16) {
        // A: 128 rows x 16 cols -> As transposed [k][m]
        #pragma unroll
        for (int i = 0; i < 2; i++) {
            int f   = tid + i * 256;
            int row = f >> 2;
            int c4  = (f & 3) * 4;
            float4 v = *(const float4*)(A + (size_t)(bm + row) * 1024 + k0 + c4);
            As[c4+0][row] = v.x; As[c4+1][row] = v.y;
            As[c4+2][row] = v.z; As[c4+3][row] = v.w;
        }
        // B: 16 rows x 128 cols
        #pragma unroll
        for (int i = 0; i < 2; i++) {
            int f   = tid + i * 256;
            int row = f >> 5;
            int c4  = (f & 31) * 4;
            *(float4*)(&Bs[row][c4]) =
                *(const float4*)(Bw + (size_t)(k0 + row) * 1024 + bn + c4);
        }
        __syncthreads();

        #pragma unroll
        for (int k = 0; k < 16; k++) {
            float a[8], b[8];
            *(float4*)(a)     = *(const float4*)(&As[k][ty*8]);
            *(float4*)(a + 4) = *(const float4*)(&As[k][ty*8 + 4]);
            *(float4*)(b)     = *(const float4*)(&Bs[k][tx*8]);
            *(float4*)(b + 4) = *(const float4*)(&Bs[k][tx*8 + 4]);
            #pragma unroll
            for (int i = 0; i < 8; i++)
                #pragma unroll
                for (int j = 0; j < 8; j++) acc[i][j] += a[i] * b[j];
        }
        __syncthreads();
    }

    #pragma unroll
    for (int i = 0; i < 8; i++) {
        float* cp = C + (size_t)(bm + ty*8 + i) * 1024 + bn + tx*8;
        *(float4*)(cp)     = make_float4(acc[i][0], acc[i][1], acc[i][2], acc[i][3]);
        *(float4*)(cp + 4) = make_float4(acc[i][4], acc[i][5], acc[i][6], acc[i][7]);
    }
}

// Fused Q,K,V projection: one launch, blockIdx.x selects {Wq,Wk,Wv} and n-tile
__global__ void qkv_gemm_kernel(const float* __restrict__ Wq,
                                const float* __restrict__ Wk,
                                const float* __restrict__ Wv) {
    int which = blockIdx.x >> 3;                // 0..2
    int bn    = (blockIdx.x & 7) * 128;
    int bm    = blockIdx.y * 128;
    const float* W = (which == 0) ? Wq : ((which == 1) ? Wk : Wv);
    float* C = g_qkv + (size_t)which * MM * DD;
    gemm_tile(g_xt, W, C, bm, bn);
}

__global__ void out_gemm_kernel(const float* __restrict__ Wo, float* __restrict__ C) {
    gemm_tile(g_attnout, Wo, C, blockIdx.y * 128, blockIdx.x * 128);
}

// ---------------------------------------------------------------------------
// Temporal attention. Mask = balanced partition -> contiguous key segment.
//   valid row i: chunk c = i*div/l, j in [ceil(c*l/div), min(l, floor(((c+1)l-1)/div)+1))
//   pad row i>=l: j in [l, T)
// One block per (i, h, b), 128 threads (= dh).
// ---------------------------------------------------------------------------
__global__ void temporal_attn_kernel(const int* __restrict__ valid_len) {
    const int i = blockIdx.x, h = blockIdx.y, b = blockIdx.z;
    const int tid = threadIdx.x;    // 128
    __shared__ float qs[128];
    __shared__ float p[TT];
    __shared__ float red[128];

    const int l = valid_len[b];
    int lo, hi;
    const int dv = (h >> 1) + 1;
    if (i < l) {
        int c  = (i * dv) / l;
        lo = (c * l + dv - 1) / dv;
        hi = ((c + 1) * l - 1) / dv + 1;
        if (hi > l) hi = l;
    } else {
        lo = l; hi = TT;
    }

    const float* Q = g_qkv;
    const float* K = g_qkv + (size_t)MM * DD;
    const float* V = g_qkv + 2 * (size_t)MM * DD;
    const size_t qoff = (size_t)(b * TT + i) * DD + h * 128;

    qs[tid] = Q[qoff + tid];
    __syncthreads();

    const int seg = hi - lo;
    const float scale = 0.08838834764831845f;   // 1/sqrt(128)

    float lmax = -3.0e38f;
    for (int jj = tid; jj < seg; jj += 128) {
        const float4* kp = (const float4*)(K + (size_t)(b * TT + lo + jj) * DD + h * 128);
        float s = 0.f;
        #pragma unroll
        for (int d = 0; d < 32; d++) {
            float4 kv = kp[d];
            float4 qv = *(const float4*)(qs + d * 4);
            s += kv.x*qv.x + kv.y*qv.y + kv.z*qv.z + kv.w*qv.w;
        }
        s *= scale;
        p[jj] = s;
        lmax = fmaxf(lmax, s);
    }
    red[tid] = lmax; __syncthreads();
    #pragma unroll
    for (int s = 64; s > 0; s >>= 1) {
        if (tid < s) red[tid] = fmaxf(red[tid], red[tid + s]);
        __syncthreads();
    }
    const float gmax = red[0];
    __syncthreads();

    float lsum = 0.f;
    for (int jj = tid; jj < seg; jj += 128) {
        float e = __expf(p[jj] - gmax);
        p[jj] = e; lsum += e;
    }
    red[tid] = lsum; __syncthreads();
    #pragma unroll
    for (int s = 64; s > 0; s >>= 1) {
        if (tid < s) red[tid] += red[tid + s];
        __syncthreads();
    }
    const float inv = 1.f / red[0];

    float acc = 0.f;
    const float* vb = V + (size_t)(b * TT + lo) * DD + h * 128 + tid;
    int j = 0;
    for (; j + 4 <= seg; j += 4) {
        acc += p[j]     * vb[(size_t)(j)     * DD];
        acc += p[j + 1] * vb[(size_t)(j + 1) * DD];
        acc += p[j + 2] * vb[(size_t)(j + 2) * DD];
        acc += p[j + 3] * vb[(size_t)(j + 3) * DD];
    }
    for (; j < seg; j++) acc += p[j] * vb[(size_t)j * DD];

    g_attnout[qoff + tid] = acc * inv;
}

// ---------------------------------------------------------------------------
extern "C" void kernel_launch(void* const* d_in, const int* in_sizes, int n_in,
                              void* d_out, int out_size) {
    const float* x   = (const float*)d_in[0];
    const float* xs  = (const float*)d_in[1];
    const int*   vl  = (const int*)  d_in[2];
    const float* Wq  = (const float*)d_in[3];
    const float* Wk  = (const float*)d_in[4];
    const float* Wv  = (const float*)d_in[5];
    const float* Wo  = (const float*)d_in[6];
    const float* Wqs = (const float*)d_in[7];
    const float* Wks = (const float*)d_in[8];
    const float* Wvs = (const float*)d_in[9];
    const float* Wos = (const float*)d_in[10];
    const float* Wt  = (const float*)d_in[11];
    float* out = (float*)d_out;

    woswt_kernel<<<256, 256>>>(Wos, Wt);
    spectral_kernel<<<MM, 256>>>(xs, Wqs, Wks, Wvs);
    xt_kernel<<<MM, 256>>>(x);
    qkv_gemm_kernel<<<dim3(24, 16), 256>>>(Wq, Wk, Wv);
    temporal_attn_kernel<<<dim3(TT, HH, BB), 128>>>(vl);
    out_gemm_kernel<<<dim3(8, 16), 256>>>(Wo, out);
}

// round 4
// speedup vs baseline: 2.5563x; 2.5563x over previous
#include <cuda_runtime.h>
#include <cstdint>

// Shapes (fixed by the problem)
#define BB   4
#define TT   512
#define FF   93
#define DSS  64
#define DD   1024
#define HH   8
#define MM   (BB*TT)      // 2048 rows

// Scratch (static device allocations; no cudaMalloc allowed)
__device__ float g_y0pre[MM*DSS];        // spectral fct output pre-Wos  [2048,64]
__device__ float g_WosWt[DSS*DD];        // Wos @ Wt                     [64,1024]
__device__ float g_xt[MM*DD];            // temporal stream input        [2048,1024]
__device__ float g_qkv[3*MM*DD];         // Q,K,V                        [3,2048,1024]
__device__ float g_attnout[MM*DD];       // temporal attention output    [2048,1024]

// ---------------------------------------------------------------------------
// helpers: tf32 convert + mma
// ---------------------------------------------------------------------------
__device__ __forceinline__ uint32_t f2tf32(float x) {
    uint32_t r;
    asm("cvt.rna.tf32.f32 %0, %1;" : "=r"(r) : "f"(x));
    return r;
}
__device__ __forceinline__ void mma_tf32(float c[4], const uint32_t a[4], const uint32_t b[2]) {
    asm volatile(
        "mma.sync.aligned.m16n8k8.row.col.f32.tf32.tf32.f32 "
        "{%0,%1,%2,%3}, {%4,%5,%6,%7}, {%8,%9}, {%0,%1,%2,%3};"
        : "+f"(c[0]), "+f"(c[1]), "+f"(c[2]), "+f"(c[3])
        : "r"(a[0]), "r"(a[1]), "r"(a[2]), "r"(a[3]), "r"(b[0]), "r"(b[1]));
}

// ---------------------------------------------------------------------------
// WosWt = Wos[64,64] @ Wt[64,1024]
// ---------------------------------------------------------------------------
__global__ void woswt_kernel(const float* __restrict__ Wos, const float* __restrict__ Wt) {
    int idx = blockIdx.x * 256 + threadIdx.x;   // 65536 outputs
    int r = idx >> 10, c = idx & 1023;
    float s = 0.f;
    #pragma unroll 8
    for (int k = 0; k < 64; k++) s += Wos[r*64 + k] * Wt[k*1024 + c];
    g_WosWt[idx] = s;
}

// ---------------------------------------------------------------------------
// Spectral attention, fct query only (row-0 mask is all-True).
// ---------------------------------------------------------------------------
__global__ void spectral_kernel(const float* __restrict__ xs,
                                const float* __restrict__ Wqs,
                                const float* __restrict__ Wks,
                                const float* __restrict__ Wvs) {
    __shared__ float xs_s[FF*65];
    __shared__ float q0_s[64];
    __shared__ float qW_s[8*64];
    __shared__ float p_s[8*96];
    __shared__ float a_s[8*64];

    const int bt  = blockIdx.x;
    const int tid = threadIdx.x;   // 256
    const float* xp = xs + (size_t)bt * FF * DSS;

    for (int idx = tid; idx < FF*DSS; idx += 256)
        xs_s[(idx >> 6) * 65 + (idx & 63)] = xp[idx];
    __syncthreads();

    if (tid < 64) {
        float s = 0.f;
        #pragma unroll 8
        for (int k = 0; k < 64; k++) s += xs_s[k] * __ldg(&Wqs[k*64 + tid]);
        q0_s[tid] = s;
    }
    __syncthreads();

    // qW[h][k] = sum_d q0[h*8+d] * Wks[k][h*8+d]
    for (int idx = tid; idx < 512; idx += 256) {
        int h = idx >> 6, k = idx & 63;
        float s = 0.f;
        #pragma unroll
        for (int d = 0; d < 8; d++) s += q0_s[h*8 + d] * __ldg(&Wks[k*64 + h*8 + d]);
        qW_s[idx] = s;
    }
    __syncthreads();

    const float scale = 0.35355339059327376f;   // 1/sqrt(8)
    for (int idx = tid; idx < 8*FF; idx += 256) {
        int h = idx / FF, j = idx - h * FF;
        float s = 0.f;
        #pragma unroll 8
        for (int k = 0; k < 64; k++) s += xs_s[j*65 + k] * qW_s[h*64 + k];
        p_s[h*96 + j] = s * scale;
    }
    __syncthreads();

    {
        int w = tid >> 5, lane = tid & 31;
        float m = -3.0e38f;
        for (int j = lane; j < FF; j += 32) m = fmaxf(m, p_s[w*96 + j]);
        #pragma unroll
        for (int o = 16; o > 0; o >>= 1) m = fmaxf(m, __shfl_xor_sync(0xffffffffu, m, o));
        float sum = 0.f;
        for (int j = lane; j < FF; j += 32) {
            float e = __expf(p_s[w*96 + j] - m);
            p_s[w*96 + j] = e; sum += e;
        }
        #pragma unroll
        for (int o = 16; o > 0; o >>= 1) sum += __shfl_xor_sync(0xffffffffu, sum, o);
        float inv = 1.f / sum;
        for (int j = lane; j < FF; j += 32) p_s[w*96 + j] *= inv;
    }
    __syncthreads();

    for (int idx = tid; idx < 512; idx += 256) {
        int h = idx >> 6, k = idx & 63;
        float s = 0.f;
        for (int j = 0; j < FF; j++) s += p_s[h*96 + j] * xs_s[j*65 + k];
        a_s[idx] = s;
    }
    __syncthreads();

    if (tid < 64) {
        int h = tid >> 3;
        float s = 0.f;
        #pragma unroll 8
        for (int k = 0; k < 64; k++) s += a_s[h*64 + k] * __ldg(&Wvs[k*64 + tid]);
        g_y0pre[bt*64 + tid] = s;
    }
}

// ---------------------------------------------------------------------------
// xt = x + y0pre @ WosWt
// ---------------------------------------------------------------------------
__global__ void xt_kernel(const float* __restrict__ x) {
    int row = blockIdx.x;
    int tid = threadIdx.x;     // 256
    __shared__ float y0[64];
    if (tid < 64) y0[tid] = g_y0pre[row*64 + tid];
    __syncthreads();

    int c = tid * 4;
    float4 acc = *(const float4*)(x + (size_t)row*DD + c);
    #pragma unroll 8
    for (int k = 0; k < 64; k++) {
        float y = y0[k];
        float4 w = *(const float4*)(g_WosWt + k*DD + c);
        acc.x += y * w.x; acc.y += y * w.y; acc.z += y * w.z; acc.w += y * w.w;
    }
    *(float4*)(g_xt + (size_t)row*DD + c) = acc;
}

// ---------------------------------------------------------------------------
// tf32 tensor-core GEMM tile: C[128,128] += A[128,1024] @ W[1024,128]
// block = 256 threads (8 warps as 4x2), warp tile 32x64, mma m16n8k8.
// ---------------------------------------------------------------------------
__device__ __forceinline__ void gemm_tf32_tile(const float* __restrict__ A,
                                               const float* __restrict__ Bw,
                                               float* __restrict__ C,
                                               int bm, int bn) {
    __shared__ float As[128][36];   // m-major, pad 36 (16B-aligned stride)
    __shared__ float Bs[32][136];   // k-major, pad 136

    const int tid  = threadIdx.x;
    const int warp = tid >> 5, lane = tid & 31;
    const int wm = (warp >> 1) * 32;   // 4 warp-rows
    const int wn = (warp & 1) * 64;    // 2 warp-cols
    const int g = lane >> 2, t = lane & 3;

    float acc[2][8][4];
    #pragma unroll
    for (int mi = 0; mi < 2; mi++)
        #pragma unroll
        for (int ni = 0; ni < 8; ni++)
            #pragma unroll
            for (int r = 0; r < 4; r++) acc[mi][ni][r] = 0.f;

    for (int k0 = 0; k0 < 1024; k0 += 32) {
        #pragma unroll
        for (int i = 0; i < 4; i++) {
            int f = tid + i * 256;
            int row = f >> 3, c4 = (f & 7) << 2;
            *(float4*)&As[row][c4] = *(const float4*)(A + (size_t)(bm + row) * 1024 + k0 + c4);
        }
        #pragma unroll
        for (int i = 0; i < 4; i++) {
            int f = tid + i * 256;
            int row = f >> 5, c4 = (f & 31) << 2;
            *(float4*)&Bs[row][c4] =
                *(const float4*)(Bw + (size_t)(k0 + row) * 1024 + bn + c4);
        }
        __syncthreads();

        #pragma unroll
        for (int kk = 0; kk < 32; kk += 8) {
            uint32_t a[2][4], b[8][2];
            #pragma unroll
            for (int mi = 0; mi < 2; mi++) {
                int m = wm + mi * 16 + g;
                a[mi][0] = f2tf32(As[m    ][kk + t]);
                a[mi][1] = f2tf32(As[m + 8][kk + t]);
                a[mi][2] = f2tf32(As[m    ][kk + t + 4]);
                a[mi][3] = f2tf32(As[m + 8][kk + t + 4]);
            }
            #pragma unroll
            for (int ni = 0; ni < 8; ni++) {
                int n = wn + ni * 8 + g;
                b[ni][0] = f2tf32(Bs[kk + t    ][n]);
                b[ni][1] = f2tf32(Bs[kk + t + 4][n]);
            }
            #pragma unroll
            for (int mi = 0; mi < 2; mi++)
                #pragma unroll
                for (int ni = 0; ni < 8; ni++)
                    mma_tf32(acc[mi][ni], a[mi], b[ni]);
        }
        __syncthreads();
    }

    #pragma unroll
    for (int mi = 0; mi < 2; mi++) {
        int row0 = bm + wm + mi * 16 + g;
        #pragma unroll
        for (int ni = 0; ni < 8; ni++) {
            int col = bn + wn + ni * 8 + t * 2;
            *(float2*)(C + (size_t)row0 * 1024 + col)       = make_float2(acc[mi][ni][0], acc[mi][ni][1]);
            *(float2*)(C + (size_t)(row0 + 8) * 1024 + col) = make_float2(acc[mi][ni][2], acc[mi][ni][3]);
        }
    }
}

__global__ void __launch_bounds__(256) qkv_gemm_kernel(const float* __restrict__ Wq,
                                                       const float* __restrict__ Wk,
                                                       const float* __restrict__ Wv) {
    int which = blockIdx.x >> 3;                // 0..2
    int bn    = (blockIdx.x & 7) * 128;
    int bm    = blockIdx.y * 128;
    const float* W = (which == 0) ? Wq : ((which == 1) ? Wk : Wv);
    float* C = g_qkv + (size_t)which * MM * DD;
    gemm_tf32_tile(g_xt, W, C, bm, bn);
}

__global__ void __launch_bounds__(256) out_gemm_kernel(const float* __restrict__ Wo, float* __restrict__ C) {
    gemm_tf32_tile(g_attnout, Wo, C, blockIdx.y * 128, blockIdx.x * 128);
}

// ---------------------------------------------------------------------------
// Temporal attention: block-diagonal flash, STATIC smem (<48KB, no attrs).
// Block = 32 contiguous queries of one (b,h); key tiles of 32; online softmax.
// K and V share one smem buffer (load K -> S phase -> load V -> PV phase).
// Thread layout: qg = tid>>4 (16 groups), kg/dg = tid&15.
// S micro: 2q x 2k. PV micro: 2q x 8d (d strided by 16).
// ---------------------------------------------------------------------------
__global__ void __launch_bounds__(256) temporal_attn_kernel(const int* __restrict__ valid_len) {
    __shared__ float Qs [32][132];
    __shared__ float KVs[32][132];
    __shared__ float Ss [32][33];
    __shared__ float m_s[32], l_s[32], al_s[32];
    __shared__ int   lo_s[32], hi_s[32];

    const int qt = blockIdx.x, h = blockIdx.y, b = blockIdx.z;
    const int tid = threadIdx.x;
    const int q0 = qt * 32;
    const float* Q = g_qkv;
    const float* K = g_qkv + (size_t)MM * DD;
    const float* V = g_qkv + 2 * (size_t)MM * DD;
    const int l = valid_len[b];

    if (tid < 32) {
        int i = q0 + tid;
        int lo, hi;
        const int dv = (h >> 1) + 1;
        if (i < l) {
            int c = (i * dv) / l;
            lo = (c * l + dv - 1) / dv;
            hi = ((c + 1) * l - 1) / dv + 1;
            if (hi > l) hi = l;
        } else { lo = l; hi = TT; }
        lo_s[tid] = lo; hi_s[tid] = hi;
        m_s[tid] = -1e30f; l_s[tid] = 0.f;
    }
    // load Q tile (32 x 128)
    for (int f = tid; f < 32*32; f += 256) {
        int r = f >> 5, c4 = (f & 31) << 2;
        *(float4*)&Qs[r][c4] =
            *(const float4*)(Q + (size_t)(b*TT + q0 + r)*DD + h*128 + c4);
    }
    __syncthreads();
    const int bLo = lo_s[0], bHi = hi_s[31];   // lo/hi monotone in i

    const int qg = tid >> 4;   // 0..15
    const int kg = tid & 15;   // also dg for PV phase
    const float scale = 0.08838834764831845f;  // 1/sqrt(128)

    float O[2][8];
    #pragma unroll
    for (int i = 0; i < 2; i++)
        #pragma unroll
        for (int d = 0; d < 8; d++) O[i][d] = 0.f;

    for (int kt = bLo & ~31; kt < bHi; kt += 32) {
        // ---- load K tile (32 x 128) ----
        for (int f = tid; f < 32*32; f += 256) {
            int r = f >> 5, c4 = (f & 31) << 2;
            int j = kt + r; if (j > TT - 1) j = TT - 1;
            *(float4*)&KVs[r][c4] =
                *(const float4*)(K + (size_t)(b*TT + j)*DD + h*128 + c4);
        }
        __syncthreads();

        // ---- S phase: S[32][32] via 2q x 2k micro-tiles ----
        float sacc[2][2];
        sacc[0][0] = sacc[0][1] = sacc[1][0] = sacc[1][1] = 0.f;
        #pragma unroll 8
        for (int d4 = 0; d4 < 32; d4++) {
            float4 kv0 = *(float4*)&KVs[kg][d4*4];
            float4 kv1 = *(float4*)&KVs[kg + 16][d4*4];
            #pragma unroll
            for (int i = 0; i < 2; i++) {
                float4 qv = *(float4*)&Qs[qg + 16*i][d4*4];
                sacc[i][0] += qv.x*kv0.x + qv.y*kv0.y + qv.z*kv0.z + qv.w*kv0.w;
                sacc[i][1] += qv.x*kv1.x + qv.y*kv1.y + qv.z*kv1.z + qv.w*kv1.w;
            }
        }
        #pragma unroll
        for (int i = 0; i < 2; i++) {
            Ss[qg + 16*i][kg]      = sacc[i][0] * scale;
            Ss[qg + 16*i][kg + 16] = sacc[i][1] * scale;
        }
        __syncthreads();

        // ---- softmax bookkeeping (tid<32, one thread per query row) ----
        if (tid < 32) {
            const int lo = lo_s[tid], hi = hi_s[tid];
            float mo = m_s[tid];
            float rmax = -3e38f;
            #pragma unroll 8
            for (int j = 0; j < 32; j++) {
                int jg = kt + j;
                float s = (jg >= lo && jg < hi) ? Ss[tid][j] : -3e38f;
                Ss[tid][j] = s;
                rmax = fmaxf(rmax, s);
            }
            float mn = fmaxf(mo, rmax);
            float alpha = __expf(mo - mn);
            float rs = 0.f;
            #pragma unroll 8
            for (int j = 0; j < 32; j++) {
                float p = __expf(Ss[tid][j] - mn);
                Ss[tid][j] = p;
                rs += p;
            }
            l_s[tid] = l_s[tid] * alpha + rs;
            m_s[tid] = mn;
            al_s[tid] = alpha;
        }
        // ---- load V tile into the same buffer (K no longer needed) ----
        for (int f = tid; f < 32*32; f += 256) {
            int r = f >> 5, c4 = (f & 31) << 2;
            int j = kt + r; if (j > TT - 1) j = TT - 1;
            *(float4*)&KVs[r][c4] =
                *(const float4*)(V + (size_t)(b*TT + j)*DD + h*128 + c4);
        }
        __syncthreads();

        // ---- PV: rescale O, then O += P @ V  (d = kg + 16*ii) ----
        #pragma unroll
        for (int i = 0; i < 2; i++) {
            float a = al_s[qg + 16*i];
            #pragma unroll
            for (int d = 0; d < 8; d++) O[i][d] *= a;
        }
        #pragma unroll 4
        for (int k = 0; k < 32; k++) {
            float vv[8];
            #pragma unroll
            for (int ii = 0; ii < 8; ii++) vv[ii] = KVs[k][kg + 16*ii];
            #pragma unroll
            for (int i = 0; i < 2; i++) {
                float p = Ss[qg + 16*i][k];
                #pragma unroll
                for (int ii = 0; ii < 8; ii++) O[i][ii] += p * vv[ii];
            }
        }
        __syncthreads();
    }

    // write out (d = kg + 16*ii)
    #pragma unroll
    for (int i = 0; i < 2; i++) {
        int q = q0 + qg + 16*i;
        float inv = 1.f / l_s[qg + 16*i];
        float* op = g_attnout + (size_t)(b*TT + q)*DD + h*128;
        #pragma unroll
        for (int ii = 0; ii < 8; ii++) op[kg + 16*ii] = O[i][ii] * inv;
    }
}

// ---------------------------------------------------------------------------
extern "C" void kernel_launch(void* const* d_in, const int* in_sizes, int n_in,
                              void* d_out, int out_size) {
    const float* x   = (const float*)d_in[0];
    const float* xs  = (const float*)d_in[1];
    const int*   vl  = (const int*)  d_in[2];
    const float* Wq  = (const float*)d_in[3];
    const float* Wk  = (const float*)d_in[4];
    const float* Wv  = (const float*)d_in[5];
    const float* Wo  = (const float*)d_in[6];
    const float* Wqs = (const float*)d_in[7];
    const float* Wks = (const float*)d_in[8];
    const float* Wvs = (const float*)d_in[9];
    const float* Wos = (const float*)d_in[10];
    const float* Wt  = (const float*)d_in[11];
    float* out = (float*)d_out;

    woswt_kernel<<<256, 256>>>(Wos, Wt);
    spectral_kernel<<<MM, 256>>>(xs, Wqs, Wks, Wvs);
    xt_kernel<<<MM, 256>>>(x);
    qkv_gemm_kernel<<<dim3(24, 16), 256>>>(Wq, Wk, Wv);
    temporal_attn_kernel<<<dim3(TT/32, HH, BB), 256>>>(vl);
    out_gemm_kernel<<<dim3(8, 16), 256>>>(Wo, out);
}

// round 5
// speedup vs baseline: 2.7439x; 1.0734x over previous
#include <cuda_runtime.h>
#include <cstdint>

// Shapes (fixed by the problem)
#define BB   4
#define TT   512
#define FF   93
#define DSS  64
#define DD   1024
#define HH   8
#define MM   (BB*TT)      // 2048 rows

// Scratch (static device allocations; no cudaMalloc allowed)
__device__ float g_y0pre[MM*DSS];        // spectral fct output pre-Wos  [2048,64]
__device__ float g_WosWt[DSS*DD];        // Wos @ Wt                     [64,1024]
__device__ float g_xt[MM*DD];            // temporal stream input        [2048,1024]
__device__ float g_qkv[3*MM*DD];         // Q,K,V                        [3,2048,1024]
__device__ float g_attnout[MM*DD];       // temporal attention output    [2048,1024]

// ---------------------------------------------------------------------------
// helpers: tf32 convert + mma
// ---------------------------------------------------------------------------
__device__ __forceinline__ uint32_t f2tf32(float x) {
    uint32_t r;
    asm("cvt.rna.tf32.f32 %0, %1;" : "=r"(r) : "f"(x));
    return r;
}
__device__ __forceinline__ void mma_tf32(float c[4], const uint32_t a[4], const uint32_t b[2]) {
    asm volatile(
        "mma.sync.aligned.m16n8k8.row.col.f32.tf32.tf32.f32 "
        "{%0,%1,%2,%3}, {%4,%5,%6,%7}, {%8,%9}, {%0,%1,%2,%3};"
        : "+f"(c[0]), "+f"(c[1]), "+f"(c[2]), "+f"(c[3])
        : "r"(a[0]), "r"(a[1]), "r"(a[2]), "r"(a[3]), "r"(b[0]), "r"(b[1]));
}

// ---------------------------------------------------------------------------
// WosWt = Wos[64,64] @ Wt[64,1024]
// ---------------------------------------------------------------------------
__global__ void woswt_kernel(const float* __restrict__ Wos, const float* __restrict__ Wt) {
    int idx = blockIdx.x * 256 + threadIdx.x;   // 65536 outputs
    int r = idx >> 10, c = idx & 1023;
    float s = 0.f;
    #pragma unroll 8
    for (int k = 0; k < 64; k++) s += Wos[r*64 + k] * Wt[k*1024 + c];
    g_WosWt[idx] = s;
}

// ---------------------------------------------------------------------------
// Spectral attention, fct query only (row-0 mask is all-True).
// ---------------------------------------------------------------------------
__global__ void spectral_kernel(const float* __restrict__ xs,
                                const float* __restrict__ Wqs,
                                const float* __restrict__ Wks,
                                const float* __restrict__ Wvs) {
    __shared__ float xs_s[FF*65];
    __shared__ float q0_s[64];
    __shared__ float qW_s[8*64];
    __shared__ float p_s[8*96];
    __shared__ float a_s[8*64];

    const int bt  = blockIdx.x;
    const int tid = threadIdx.x;   // 256
    const float* xp = xs + (size_t)bt * FF * DSS;

    for (int idx = tid; idx < FF*DSS; idx += 256)
        xs_s[(idx >> 6) * 65 + (idx & 63)] = xp[idx];
    __syncthreads();

    if (tid < 64) {
        float s = 0.f;
        #pragma unroll 8
        for (int k = 0; k < 64; k++) s += xs_s[k] * __ldg(&Wqs[k*64 + tid]);
        q0_s[tid] = s;
    }
    __syncthreads();

    // qW[h][k] = sum_d q0[h*8+d] * Wks[k][h*8+d]
    for (int idx = tid; idx < 512; idx += 256) {
        int h = idx >> 6, k = idx & 63;
        float s = 0.f;
        #pragma unroll
        for (int d = 0; d < 8; d++) s += q0_s[h*8 + d] * __ldg(&Wks[k*64 + h*8 + d]);
        qW_s[idx] = s;
    }
    __syncthreads();

    const float scale = 0.35355339059327376f;   // 1/sqrt(8)
    for (int idx = tid; idx < 8*FF; idx += 256) {
        int h = idx / FF, j = idx - h * FF;
        float s = 0.f;
        #pragma unroll 8
        for (int k = 0; k < 64; k++) s += xs_s[j*65 + k] * qW_s[h*64 + k];
        p_s[h*96 + j] = s * scale;
    }
    __syncthreads();

    {
        int w = tid >> 5, lane = tid & 31;
        float m = -3.0e38f;
        for (int j = lane; j < FF; j += 32) m = fmaxf(m, p_s[w*96 + j]);
        #pragma unroll
        for (int o = 16; o > 0; o >>= 1) m = fmaxf(m, __shfl_xor_sync(0xffffffffu, m, o));
        float sum = 0.f;
        for (int j = lane; j < FF; j += 32) {
            float e = __expf(p_s[w*96 + j] - m);
            p_s[w*96 + j] = e; sum += e;
        }
        #pragma unroll
        for (int o = 16; o > 0; o >>= 1) sum += __shfl_xor_sync(0xffffffffu, sum, o);
        float inv = 1.f / sum;
        for (int j = lane; j < FF; j += 32) p_s[w*96 + j] *= inv;
    }
    __syncthreads();

    for (int idx = tid; idx < 512; idx += 256) {
        int h = idx >> 6, k = idx & 63;
        float s = 0.f;
        for (int j = 0; j < FF; j++) s += p_s[h*96 + j] * xs_s[j*65 + k];
        a_s[idx] = s;
    }
    __syncthreads();

    if (tid < 64) {
        int h = tid >> 3;
        float s = 0.f;
        #pragma unroll 8
        for (int k = 0; k < 64; k++) s += a_s[h*64 + k] * __ldg(&Wvs[k*64 + tid]);
        g_y0pre[bt*64 + tid] = s;
    }
}

// ---------------------------------------------------------------------------
// xt = x + y0pre @ WosWt.  16 rows per block to amortize WosWt reads.
// ---------------------------------------------------------------------------
__global__ void __launch_bounds__(256) xt_kernel(const float* __restrict__ x) {
    const int r0  = blockIdx.x * 16;
    const int tid = threadIdx.x;     // 256
    __shared__ float y0[16][64];

    for (int idx = tid; idx < 16*64; idx += 256)
        y0[idx >> 6][idx & 63] = g_y0pre[(r0 + (idx >> 6)) * 64 + (idx & 63)];
    __syncthreads();

    const int c = tid * 4;
    float4 acc[16];
    #pragma unroll
    for (int r = 0; r < 16; r++)
        acc[r] = *(const float4*)(x + (size_t)(r0 + r) * DD + c);

    #pragma unroll 4
    for (int k = 0; k < 64; k++) {
        float4 w = *(const float4*)(g_WosWt + k * DD + c);
        #pragma unroll
        for (int r = 0; r < 16; r++) {
            float y = y0[r][k];
            acc[r].x += y * w.x; acc[r].y += y * w.y;
            acc[r].z += y * w.z; acc[r].w += y * w.w;
        }
    }
    #pragma unroll
    for (int r = 0; r < 16; r++)
        *(float4*)(g_xt + (size_t)(r0 + r) * DD + c) = acc[r];
}

// ---------------------------------------------------------------------------
// tf32 tensor-core GEMM tile: C[128,128] += A[128,1024] @ W[1024,128]
// smem holds PRE-CONVERTED tf32 bits; inner loop = LDS + MMA only.
// Register double-buffering: prefetch next k-tile during mma block.
// block = 256 threads (8 warps as 4x2), warp tile 32x64, mma m16n8k8.
// ---------------------------------------------------------------------------
__device__ __forceinline__ void gemm_tf32_tile(const float* __restrict__ A,
                                               const float* __restrict__ Bw,
                                               float* __restrict__ C,
                                               int bm, int bn) {
    __shared__ uint32_t As[128][36];   // m-major tf32 bits, pad 36
    __shared__ uint32_t Bs[32][136];   // k-major tf32 bits, pad 136

    const int tid  = threadIdx.x;
    const int warp = tid >> 5, lane = tid & 31;
    const int wm = (warp >> 1) * 32;   // 4 warp-rows
    const int wn = (warp & 1) * 64;    // 2 warp-cols
    const int g = lane >> 2, t = lane & 3;

    // per-thread load coordinates (fixed)
    const int aRow0 = tid >> 3,        aC = (tid & 7) << 2;          // +64 rows per i
    const int bRow0 = tid >> 5,        bC = (tid & 31) << 2;         // +8 rows per i

    float4 pa[2], pb[4];   // A: 2 float4/thread (rows aRow0, aRow0+64); B: 4 float4/thread
    // NOTE: A tile is 128x32 = 4096 float4 / 256 thr = 4 each. Use 4 for A too.
    float4 pa2[2];

    auto loadA = [&](int k0) {
        pa[0]  = *(const float4*)(A + (size_t)(bm + aRow0      ) * 1024 + k0 + aC);
        pa[1]  = *(const float4*)(A + (size_t)(bm + aRow0 + 32 ) * 1024 + k0 + aC);
        pa2[0] = *(const float4*)(A + (size_t)(bm + aRow0 + 64 ) * 1024 + k0 + aC);
        pa2[1] = *(const float4*)(A + (size_t)(bm + aRow0 + 96 ) * 1024 + k0 + aC);
    };
    auto loadB = [&](int k0) {
        #pragma unroll
        for (int i = 0; i < 4; i++)
            pb[i] = *(const float4*)(Bw + (size_t)(k0 + bRow0 + 8*i) * 1024 + bn + bC);
    };
    auto storeTiles = [&]() {
        #pragma unroll
        for (int i = 0; i < 2; i++) {
            float4 v = pa[i];
            uint32_t* p = &As[aRow0 + 32*i][aC];
            p[0]=f2tf32(v.x); p[1]=f2tf32(v.y); p[2]=f2tf32(v.z); p[3]=f2tf32(v.w);
            v = pa2[i];
            p = &As[aRow0 + 64 + 32*i][aC];
            p[0]=f2tf32(v.x); p[1]=f2tf32(v.y); p[2]=f2tf32(v.z); p[3]=f2tf32(v.w);
        }
        #pragma unroll
        for (int i = 0; i < 4; i++) {
            float4 v = pb[i];
            uint32_t* p = &Bs[bRow0 + 8*i][bC];
            p[0]=f2tf32(v.x); p[1]=f2tf32(v.y); p[2]=f2tf32(v.z); p[3]=f2tf32(v.w);
        }
    };

    float acc[2][8][4];
    #pragma unroll
    for (int mi = 0; mi < 2; mi++)
        #pragma unroll
        for (int ni = 0; ni < 8; ni++)
            #pragma unroll
            for (int r = 0; r < 4; r++) acc[mi][ni][r] = 0.f;

    loadA(0); loadB(0); storeTiles();
    __syncthreads();

    for (int k0 = 0; k0 < 1024; k0 += 32) {
        const bool more = (k0 + 32) < 1024;
        if (more) { loadA(k0 + 32); loadB(k0 + 32); }   // overlap with mma below

        #pragma unroll
        for (int kk = 0; kk < 32; kk += 8) {
            uint32_t a[2][4], b[8][2];
            #pragma unroll
            for (int mi = 0; mi < 2; mi++) {
                int m = wm + mi * 16 + g;
                a[mi][0] = As[m    ][kk + t];
                a[mi][1] = As[m + 8][kk + t];
                a[mi][2] = As[m    ][kk + t + 4];
                a[mi][3] = As[m + 8][kk + t + 4];
            }
            #pragma unroll
            for (int ni = 0; ni < 8; ni++) {
                int n = wn + ni * 8 + g;
                b[ni][0] = Bs[kk + t    ][n];
                b[ni][1] = Bs[kk + t + 4][n];
            }
            #pragma unroll
            for (int mi = 0; mi < 2; mi++)
                #pragma unroll
                for (int ni = 0; ni < 8; ni++)
                    mma_tf32(acc[mi][ni], a[mi], b[ni]);
        }
        __syncthreads();
        if (more) { storeTiles(); __syncthreads(); }
    }

    #pragma unroll
    for (int mi = 0; mi < 2; mi++) {
        int row0 = bm + wm + mi * 16 + g;
        #pragma unroll
        for (int ni = 0; ni < 8; ni++) {
            int col = bn + wn + ni * 8 + t * 2;
            *(float2*)(C + (size_t)row0 * 1024 + col)       = make_float2(acc[mi][ni][0], acc[mi][ni][1]);
            *(float2*)(C + (size_t)(row0 + 8) * 1024 + col) = make_float2(acc[mi][ni][2], acc[mi][ni][3]);
        }
    }
}

__global__ void __launch_bounds__(256, 2) qkv_gemm_kernel(const float* __restrict__ Wq,
                                                          const float* __restrict__ Wk,
                                                          const float* __restrict__ Wv) {
    int which = blockIdx.x >> 3;                // 0..2
    int bn    = (blockIdx.x & 7) * 128;
    int bm    = blockIdx.y * 128;
    const float* W = (which == 0) ? Wq : ((which == 1) ? Wk : Wv);
    float* C = g_qkv + (size_t)which * MM * DD;
    gemm_tf32_tile(g_xt, W, C, bm, bn);
}

__global__ void __launch_bounds__(256, 2) out_gemm_kernel(const float* __restrict__ Wo, float* __restrict__ C) {
    gemm_tf32_tile(g_attnout, Wo, C, blockIdx.y * 128, blockIdx.x * 128);
}

// ---------------------------------------------------------------------------
// Temporal attention: block-diagonal flash, STATIC smem (<48KB, no attrs).
// Block = 32 contiguous queries of one (b,h); key tiles of 32; online softmax.
// K and V share one smem buffer (load K -> S phase -> load V -> PV phase).
// ---------------------------------------------------------------------------
__global__ void __launch_bounds__(256) temporal_attn_kernel(const int* __restrict__ valid_len) {
    __shared__ float Qs [32][132];
    __shared__ float KVs[32][132];
    __shared__ float Ss [32][33];
    __shared__ float m_s[32], l_s[32], al_s[32];
    __shared__ int   lo_s[32], hi_s[32];

    const int qt = blockIdx.x, h = blockIdx.y, b = blockIdx.z;
    const int tid = threadIdx.x;
    const int q0 = qt * 32;
    const float* Q = g_qkv;
    const float* K = g_qkv + (size_t)MM * DD;
    const float* V = g_qkv + 2 * (size_t)MM * DD;
    const int l = valid_len[b];

    if (tid < 32) {
        int i = q0 + tid;
        int lo, hi;
        const int dv = (h >> 1) + 1;
        if (i < l) {
            int c = (i * dv) / l;
            lo = (c * l + dv - 1) / dv;
            hi = ((c + 1) * l - 1) / dv + 1;
            if (hi > l) hi = l;
        } else { lo = l; hi = TT; }
        lo_s[tid] = lo; hi_s[tid] = hi;
        m_s[tid] = -1e30f; l_s[tid] = 0.f;
    }
    for (int f = tid; f < 32*32; f += 256) {
        int r = f >> 5, c4 = (f & 31) << 2;
        *(float4*)&Qs[r][c4] =
            *(const float4*)(Q + (size_t)(b*TT + q0 + r)*DD + h*128 + c4);
    }
    __syncthreads();
    const int bLo = lo_s[0], bHi = hi_s[31];   // lo/hi monotone in i

    const int qg = tid >> 4;   // 0..15
    const int kg = tid & 15;   // also dg for PV phase
    const float scale = 0.08838834764831845f;  // 1/sqrt(128)

    float O[2][8];
    #pragma unroll
    for (int i = 0; i < 2; i++)
        #pragma unroll
        for (int d = 0; d < 8; d++) O[i][d] = 0.f;

    for (int kt = bLo & ~31; kt < bHi; kt += 32) {
        for (int f = tid; f < 32*32; f += 256) {
            int r = f >> 5, c4 = (f & 31) << 2;
            int j = kt + r; if (j > TT - 1) j = TT - 1;
            *(float4*)&KVs[r][c4] =
                *(const float4*)(K + (size_t)(b*TT + j)*DD + h*128 + c4);
        }
        __syncthreads();

        float sacc[2][2];
        sacc[0][0] = sacc[0][1] = sacc[1][0] = sacc[1][1] = 0.f;
        #pragma unroll 8
        for (int d4 = 0; d4 < 32; d4++) {
            float4 kv0 = *(float4*)&KVs[kg][d4*4];
            float4 kv1 = *(float4*)&KVs[kg + 16][d4*4];
            #pragma unroll
            for (int i = 0; i < 2; i++) {
                float4 qv = *(float4*)&Qs[qg + 16*i][d4*4];
                sacc[i][0] += qv.x*kv0.x + qv.y*kv0.y + qv.z*kv0.z + qv.w*kv0.w;
                sacc[i][1] += qv.x*kv1.x + qv.y*kv1.y + qv.z*kv1.z + qv.w*kv1.w;
            }
        }
        #pragma unroll
        for (int i = 0; i < 2; i++) {
            Ss[qg + 16*i][kg]      = sacc[i][0] * scale;
            Ss[qg + 16*i][kg + 16] = sacc[i][1] * scale;
        }
        __syncthreads();

        if (tid < 32) {
            const int lo = lo_s[tid], hi = hi_s[tid];
            float mo = m_s[tid];
            float rmax = -3e38f;
            #pragma unroll 8
            for (int j = 0; j < 32; j++) {
                int jg = kt + j;
                float s = (jg >= lo && jg < hi) ? Ss[tid][j] : -3e38f;
                Ss[tid][j] = s;
                rmax = fmaxf(rmax, s);
            }
            float mn = fmaxf(mo, rmax);
            float alpha = __expf(mo - mn);
            float rs = 0.f;
            #pragma unroll 8
            for (int j = 0; j < 32; j++) {
                float p = __expf(Ss[tid][j] - mn);
                Ss[tid][j] = p;
                rs += p;
            }
            l_s[tid] = l_s[tid] * alpha + rs;
            m_s[tid] = mn;
            al_s[tid] = alpha;
        }
        for (int f = tid; f < 32*32; f += 256) {
            int r = f >> 5, c4 = (f & 31) << 2;
            int j = kt + r; if (j > TT - 1) j = TT - 1;
            *(float4*)&KVs[r][c4] =
                *(const float4*)(V + (size_t)(b*TT + j)*DD + h*128 + c4);
        }
        __syncthreads();

        #pragma unroll
        for (int i = 0; i < 2; i++) {
            float a = al_s[qg + 16*i];
            #pragma unroll
            for (int d = 0; d < 8; d++) O[i][d] *= a;
        }
        #pragma unroll 4
        for (int k = 0; k < 32; k++) {
            float vv[8];
            #pragma unroll
            for (int ii = 0; ii < 8; ii++) vv[ii] = KVs[k][kg + 16*ii];
            #pragma unroll
            for (int i = 0; i < 2; i++) {
                float p = Ss[qg + 16*i][k];
                #pragma unroll
                for (int ii = 0; ii < 8; ii++) O[i][ii] += p * vv[ii];
            }
        }
        __syncthreads();
    }

    #pragma unroll
    for (int i = 0; i < 2; i++) {
        int q = q0 + qg + 16*i;
        float inv = 1.f / l_s[qg + 16*i];
        float* op = g_attnout + (size_t)(b*TT + q)*DD + h*128;
        #pragma unroll
        for (int ii = 0; ii < 8; ii++) op[kg + 16*ii] = O[i][ii] * inv;
    }
}

// ---------------------------------------------------------------------------
extern "C" void kernel_launch(void* const* d_in, const int* in_sizes, int n_in,
                              void* d_out, int out_size) {
    const float* x   = (const float*)d_in[0];
    const float* xs  = (const float*)d_in[1];
    const int*   vl  = (const int*)  d_in[2];
    const float* Wq  = (const float*)d_in[3];
    const float* Wk  = (const float*)d_in[4];
    const float* Wv  = (const float*)d_in[5];
    const float* Wo  = (const float*)d_in[6];
    const float* Wqs = (const float*)d_in[7];
    const float* Wks = (const float*)d_in[8];
    const float* Wvs = (const float*)d_in[9];
    const float* Wos = (const float*)d_in[10];
    const float* Wt  = (const float*)d_in[11];
    float* out = (float*)d_out;

    woswt_kernel<<<256, 256>>>(Wos, Wt);
    spectral_kernel<<<MM, 256>>>(xs, Wqs, Wks, Wvs);
    xt_kernel<<<MM/16, 256>>>(x);
    qkv_gemm_kernel<<<dim3(24, 16), 256>>>(Wq, Wk, Wv);
    temporal_attn_kernel<<<dim3(TT/32, HH, BB), 256>>>(vl);
    out_gemm_kernel<<<dim3(8, 16), 256>>>(Wo, out);
}